// round 1
// baseline (speedup 1.0000x reference)
#include <cuda_runtime.h>
#include <math.h>

#define E    11
#define KSEL 6
#define P    64
#define NH   4
#define HD   16
#define SEQ  12
#define BB   8
#define C    128
#define HH   64
#define WW   64
#define HW   (HH*WW)        /* 4096  */
#define NPIX (BB*HW)        /* 32768 */
#define HID  512
#define TILE 32
#define HSTR 36             /* padded hs row stride (floats), 16B-aligned, reduces STS conflicts */

// ---------------- device scratch (no allocation allowed) ----------------
__device__ float g_gc[BB*C];
__device__ float g_up[BB*E*P];
__device__ float g_Wr[BB*E*C];
__device__ float g_br[BB*E];
__device__ float g_route[E*NPIX];
__device__ float g_probsum[E];
__device__ float g_loadsum[E];

// ---------------- kernel 0: global-context means + zero accumulators ----
__global__ void k_gc(const float* __restrict__ x) {
    int bc = blockIdx.x;                       // 0..B*C-1
    const float4* src = reinterpret_cast<const float4*>(x + (size_t)bc * HW);
    float s = 0.f;
    for (int i = threadIdx.x; i < HW/4; i += 128) {
        float4 v = src[i];
        s += v.x + v.y + v.z + v.w;
    }
    __shared__ float red[4];
    for (int o = 16; o; o >>= 1) s += __shfl_down_sync(0xffffffffu, s, o);
    if ((threadIdx.x & 31) == 0) red[threadIdx.x >> 5] = s;
    __syncthreads();
    if (threadIdx.x == 0) {
        float t = red[0] + red[1] + red[2] + red[3];
        g_gc[bc] = t * (1.0f / HW);
    }
    if (bc == 0 && threadIdx.x < E) {
        g_probsum[threadIdx.x] = 0.f;
        g_loadsum[threadIdx.x] = 0.f;
    }
}

// ---------------- kernel A: attention path + router weight folding ------
__global__ void k_attn(const float* __restrict__ proto,
                       const float* __restrict__ ctx_w, const float* __restrict__ ctx_b,
                       const float* __restrict__ inp_w, const float* __restrict__ inp_b,
                       const float* __restrict__ wq, const float* __restrict__ bq,
                       const float* __restrict__ wk, const float* __restrict__ bk,
                       const float* __restrict__ wv, const float* __restrict__ bv,
                       const float* __restrict__ wo, const float* __restrict__ bo,
                       const float* __restrict__ ln_g, const float* __restrict__ ln_b) {
    int b = blockIdx.x;
    int t = threadIdx.x;                       // 64 threads
    __shared__ float seq[SEQ][P], qs[SEQ][P], ks[SEQ][P], vs[SEQ][P], ao[SEQ][P], o2[SEQ][P];
    __shared__ float gx[C];
    __shared__ float mstat[SEQ], istat[SEQ];

    for (int c = t; c < C; c += 64) gx[c] = g_gc[b*C + c];
    __syncthreads();

    { // gc projection -> seq[0]
        float a = ctx_b[t];
        for (int c = 0; c < C; c++) a += gx[c] * ctx_w[t*C + c];
        seq[0][t] = a;
    }
    for (int s = 1; s < SEQ; s++) seq[s][t] = proto[(s-1)*P + t];
    __syncthreads();

    for (int s = 0; s < SEQ; s++) {
        float aq = bq[t], ak = bk[t], av = bv[t];
        for (int p = 0; p < P; p++) {
            float sv = seq[s][p];
            aq += sv * wq[t*P + p];
            ak += sv * wk[t*P + p];
            av += sv * wv[t*P + p];
        }
        qs[s][t] = aq; ks[s][t] = ak; vs[s][t] = av;
    }
    __syncthreads();

    if (t < NH*SEQ) {                          // one (head, query) per thread
        int n = t / SEQ, i = t % SEQ;
        float sc[SEQ];
        float mx = -1e30f;
        for (int j = 0; j < SEQ; j++) {
            float a = 0.f;
            for (int d = 0; d < HD; d++) a += qs[i][n*HD + d] * ks[j][n*HD + d];
            a *= 0.25f;                        // 1/sqrt(HD)
            sc[j] = a; mx = fmaxf(mx, a);
        }
        float sm = 0.f;
        for (int j = 0; j < SEQ; j++) { sc[j] = expf(sc[j] - mx); sm += sc[j]; }
        float inv = 1.0f / sm;
        for (int d = 0; d < HD; d++) {
            float a = 0.f;
            for (int j = 0; j < SEQ; j++) a += sc[j] * vs[j][n*HD + d];
            ao[i][n*HD + d] = a * inv;
        }
    }
    __syncthreads();

    for (int s = 0; s < SEQ; s++) {
        float a = bo[t];
        for (int p = 0; p < P; p++) a += ao[s][p] * wo[t*P + p];
        o2[s][t] = a + seq[s][t];              // residual
    }
    __syncthreads();

    if (t < SEQ) {
        float m = 0.f;
        for (int p = 0; p < P; p++) m += o2[t][p];
        m *= (1.0f / P);
        float v = 0.f;
        for (int p = 0; p < P; p++) { float d = o2[t][p] - m; v += d*d; }
        v *= (1.0f / P);
        mstat[t] = m; istat[t] = 1.0f / sqrtf(v + 1e-5f);
    }
    __syncthreads();

    for (int s = 1; s < SEQ; s++) {
        float val = (o2[s][t] - mstat[s]) * istat[s] * ln_g[t] + ln_b[t];
        g_up[(b*E + (s-1))*P + t] = val;
        seq[s][t] = val;                       // reuse smem as "up"
    }
    __syncthreads();

    // fold inp_w into per-(b,e) router vectors: Wr[e][c] = sum_p up[e][p]*inp_w[p][c]
    for (int idx = t; idx < E*C; idx += 64) {
        int e = idx / C, c = idx % C;
        float a = 0.f;
        for (int p = 0; p < P; p++) a += seq[e+1][p] * inp_w[p*C + c];
        g_Wr[(b*E + e)*C + c] = a;
    }
    if (t < E) {
        float a = 0.f;
        for (int p = 0; p < P; p++) a += seq[t+1][p] * inp_b[p];
        g_br[b*E + t] = a;
    }
}

// ---------------- kernel B: routing (softmax + top-6) per pixel ---------
__global__ void k_route(const float* __restrict__ x) {
    int pix = blockIdx.x * 256 + threadIdx.x;  // 32768
    int b = pix / HW;
    __shared__ float wr[E*C];
    __shared__ float br[E];
    __shared__ float psum[E], lsum[E];
    for (int i = threadIdx.x; i < E*C; i += 256) wr[i] = g_Wr[b*E*C + i];
    if (threadIdx.x < E) {
        br[threadIdx.x] = g_br[b*E + threadIdx.x];
        psum[threadIdx.x] = 0.f; lsum[threadIdx.x] = 0.f;
    }
    __syncthreads();

    float pr[E];
    #pragma unroll
    for (int e = 0; e < E; e++) pr[e] = br[e];
    const float* xp = x + (size_t)b*C*HW + (pix - b*HW);
    for (int c = 0; c < C; c++) {
        float xv = xp[(size_t)c * HW];
        #pragma unroll
        for (int e = 0; e < E; e++) pr[e] += xv * wr[e*C + c];
    }
    float mx = -1e30f;
    #pragma unroll
    for (int e = 0; e < E; e++) { pr[e] *= 0.125f; mx = fmaxf(mx, pr[e]); }
    float sm = 0.f;
    #pragma unroll
    for (int e = 0; e < E; e++) { pr[e] = expf(pr[e] - mx); sm += pr[e]; }
    float invs = 1.0f / sm;
    #pragma unroll
    for (int e = 0; e < E; e++) pr[e] *= invs;     // probs

    // top-6 (first index wins ties, matching lax.top_k)
    int used = 0;
    float tsum = 0.f;
    #pragma unroll
    for (int k2 = 0; k2 < KSEL; k2++) {
        float bv = -1.f; int bi = 0;
        #pragma unroll
        for (int e = 0; e < E; e++)
            if (!((used >> e) & 1) && pr[e] > bv) { bv = pr[e]; bi = e; }
        used |= 1 << bi;
        tsum += bv;
    }
    float invt = 1.0f / tsum;
    #pragma unroll
    for (int e = 0; e < E; e++) {
        int selq = (used >> e) & 1;
        g_route[(size_t)e * NPIX + pix] = selq ? pr[e] * invt : 0.f;
        atomicAdd(&psum[e], pr[e]);
        if (selq) atomicAdd(&lsum[e], 1.f);
    }
    __syncthreads();
    if (threadIdx.x < E) {
        atomicAdd(&g_probsum[threadIdx.x], psum[threadIdx.x]);
        atomicAdd(&g_loadsum[threadIdx.x], lsum[threadIdx.x]);
    }
}

// ---------------- kernel C: sparse expert MLPs ---------------------------
__global__ void __launch_bounds__(256, 2)
k_expert(const float* __restrict__ x,
         const float* __restrict__ ew1, const float* __restrict__ eb1,
         const float* __restrict__ ew2, const float* __restrict__ eb2,
         float* __restrict__ out) {
    extern __shared__ float smem[];
    float* xs   = smem;                 // [C][TILE]      4096
    float* xsel = xs   + C*TILE;        // [C][TILE]      4096  (also phase-2 reduce scratch)
    float* acc  = xsel + C*TILE;        // [C][TILE]      4096
    float* hs   = acc  + C*TILE;        // [256][HSTR]    9216
    __shared__ int   sel[TILE];
    __shared__ float wt[TILE];
    __shared__ int   mcnt;

    const int tid  = threadIdx.x;
    const int pix0 = blockIdx.x * TILE;
    const int b    = pix0 / HW;
    const int off  = pix0 - b*HW;
    const float* xb = x + (size_t)b*C*HW + off;

    for (int idx = tid; idx < C*TILE; idx += 256) {
        int c = idx >> 5, i = idx & 31;
        xs[idx]  = xb[(size_t)c * HW + i];
        acc[idx] = 0.f;
    }

    const int cc = tid & (C-1);
    const int jh = tid >> 7;

    for (int e = 0; e < E; e++) {
        __syncthreads();                       // protect sel/wt/hs/xsel from prev iter
        if (tid == 0) {
            int m = 0;
            #pragma unroll
            for (int i = 0; i < TILE; i++) {
                float w = g_route[(size_t)e * NPIX + pix0 + i];
                if (w > 0.f) { sel[m] = i; wt[m] = w; m++; }
            }
            int mpad = (m + 7) & ~7;
            for (int i = m; i < mpad; i++) { sel[i] = 0; wt[i] = 0.f; }
            mcnt = m;
        }
        __syncthreads();
        const int m = mcnt;
        if (m == 0) continue;
        const int mp = (m + 7) & ~7;
        const int G  = mp >> 3;

        // compact selected pixels: xsel[c][s] = xs[c][sel[s]]
        for (int idx = tid; idx < C*TILE; idx += 256) {
            int s2 = idx & 31;
            if (s2 < mp) xsel[idx] = xs[(idx & ~31) + sel[s2]];
        }

        float y[TILE];
        #pragma unroll
        for (int i = 0; i < TILE; i++) y[i] = 0.f;

        for (int half = 0; half < 2; half++) {
            __syncthreads();                   // xsel ready / prev phase-2 hs reads done

            // ---- phase 1: h = gelu(W1 x + b1), rows [half*256, +256), 1 row/thread
            {
                const int rr = half*256 + tid;
                const float4* w1 = reinterpret_cast<const float4*>(
                    ew1 + ((size_t)e*HID + rr)*C);
                float a[TILE];
                #pragma unroll
                for (int i = 0; i < TILE; i++) a[i] = 0.f;
                #pragma unroll 2
                for (int c4 = 0; c4 < C/4; c4++) {
                    float4 w = w1[c4];
                    #pragma unroll
                    for (int q = 0; q < 4; q++) {
                        float wv = (q==0)?w.x:(q==1)?w.y:(q==2)?w.z:w.w;
                        const float4* xv = reinterpret_cast<const float4*>(
                            xsel + (c4*4 + q)*TILE);
                        #pragma unroll
                        for (int g = 0; g < TILE/8; g++) {
                            if (g < G) {
                                float4 u0 = xv[2*g], u1 = xv[2*g+1];
                                a[g*8+0] += wv*u0.x; a[g*8+1] += wv*u0.y;
                                a[g*8+2] += wv*u0.z; a[g*8+3] += wv*u0.w;
                                a[g*8+4] += wv*u1.x; a[g*8+5] += wv*u1.y;
                                a[g*8+6] += wv*u1.z; a[g*8+7] += wv*u1.w;
                            }
                        }
                    }
                }
                float b1 = eb1[(size_t)e*HID + rr];
                #pragma unroll
                for (int s2 = 0; s2 < TILE; s2++) {
                    if (s2 < 8*G) {
                        float v = a[s2] + b1;
                        hs[tid*HSTR + s2] = 0.5f*v*(1.0f + erff(v*0.70710678118654752f));
                    }
                }
            }
            __syncthreads();                   // hs ready

            // ---- phase 2 partial: y[c] += W2[c, j-slice] * h   (j-slice: 128/thread-half)
            {
                const float4* w2 = reinterpret_cast<const float4*>(
                    ew2 + ((size_t)e*C + cc)*HID + half*256 + jh*128);
                #pragma unroll 2
                for (int j4 = 0; j4 < 32; j4++) {
                    float4 w = w2[j4];
                    int jl = jh*128 + j4*4;    // local hs row
                    #pragma unroll
                    for (int q = 0; q < 4; q++) {
                        float wv = (q==0)?w.x:(q==1)?w.y:(q==2)?w.z:w.w;
                        const float4* hv = reinterpret_cast<const float4*>(
                            hs + (jl + q)*HSTR);
                        #pragma unroll
                        for (int g = 0; g < TILE/8; g++) {
                            if (g < G) {
                                float4 u0 = hv[2*g], u1 = hv[2*g+1];
                                y[g*8+0] += wv*u0.x; y[g*8+1] += wv*u0.y;
                                y[g*8+2] += wv*u0.z; y[g*8+3] += wv*u0.w;
                                y[g*8+4] += wv*u1.x; y[g*8+5] += wv*u1.y;
                                y[g*8+6] += wv*u1.z; y[g*8+7] += wv*u1.w;
                            }
                        }
                    }
                }
            }
        }

        // reduce the two j-halves and accumulate into acc
        if (jh == 1) {
            #pragma unroll
            for (int s2 = 0; s2 < TILE; s2++)
                if (s2 < mp) xsel[cc*TILE + s2] = y[s2];
        }
        __syncthreads();
        if (jh == 0) {
            float b2v = eb2[(size_t)e*C + cc];
            #pragma unroll
            for (int s2 = 0; s2 < TILE; s2++) {
                if (s2 < m) {
                    float tot = y[s2] + xsel[cc*TILE + s2] + b2v;
                    acc[cc*TILE + sel[s2]] += wt[s2] * tot;
                }
            }
        }
    }
    __syncthreads();

    float* ob = out + (size_t)b*C*HW + off;
    for (int idx = tid; idx < C*TILE; idx += 256) {
        int c = idx >> 5, i = idx & 31;
        ob[(size_t)c * HW + i] = xs[idx] + acc[idx];
    }
}

// ---------------- kernel D: aux scalar -----------------------------------
__global__ void k_aux(const float* __restrict__ proto, float* __restrict__ out, int out_size) {
    __shared__ float pn[E][P];
    __shared__ float red[128];
    int t = threadIdx.x;                       // 128 threads
    if (t < E) {
        float s = 0.f;
        for (int p = 0; p < P; p++) { float v = proto[t*P + p]; s += v*v; }
        float inv = 1.0f / sqrtf(s);
        for (int p = 0; p < P; p++) pn[t][p] = proto[t*P + p] * inv;
    }
    __syncthreads();
    float s = 0.f;
    for (int idx = t; idx < E*E; idx += 128) {
        int i = idx / E, j = idx % E;
        float d = 0.f;
        for (int p = 0; p < P; p++) d += pn[i][p] * pn[j][p];
        d -= (i == j) ? 1.0f : 0.0f;
        s += d*d;
    }
    red[t] = s;
    __syncthreads();
    for (int st = 64; st; st >>= 1) { if (t < st) red[t] += red[t + st]; __syncthreads(); }
    if (t == 0) {
        float ortho = sqrtf(red[0]);
        float aux = 0.f;
        for (int e = 0; e < E; e++)
            aux += (g_probsum[e] * (1.0f/NPIX)) * (g_loadsum[e] * (1.0f/NPIX));
        aux *= (float)E;
        if (out_size > BB*C*HW) out[BB*C*HW] = aux + 0.5f * ortho;
    }
}

// ---------------- launcher ------------------------------------------------
extern "C" void kernel_launch(void* const* d_in, const int* in_sizes, int n_in,
                              void* d_out, int out_size) {
    const float* x      = (const float*)d_in[0];
    const float* proto  = (const float*)d_in[1];
    const float* ctx_w  = (const float*)d_in[2];
    const float* ctx_b  = (const float*)d_in[3];
    const float* inp_w  = (const float*)d_in[4];
    const float* inp_b  = (const float*)d_in[5];
    const float* wq     = (const float*)d_in[6];
    const float* bq     = (const float*)d_in[7];
    const float* wk     = (const float*)d_in[8];
    const float* bk     = (const float*)d_in[9];
    const float* wv     = (const float*)d_in[10];
    const float* bv     = (const float*)d_in[11];
    const float* wo     = (const float*)d_in[12];
    const float* bo     = (const float*)d_in[13];
    const float* ln_g   = (const float*)d_in[14];
    const float* ln_b   = (const float*)d_in[15];
    const float* ew1    = (const float*)d_in[16];
    const float* eb1    = (const float*)d_in[17];
    const float* ew2    = (const float*)d_in[18];
    const float* eb2    = (const float*)d_in[19];
    float* out = (float*)d_out;

    const int smem_expert = (3*C*TILE + 256*HSTR) * (int)sizeof(float);  // 86016 B
    cudaFuncSetAttribute(k_expert, cudaFuncAttributeMaxDynamicSharedMemorySize, smem_expert);

    k_gc<<<BB*C, 128>>>(x);
    k_attn<<<BB, 64>>>(proto, ctx_w, ctx_b, inp_w, inp_b,
                       wq, bq, wk, bk, wv, bv, wo, bo, ln_g, ln_b);
    k_route<<<NPIX/256, 256>>>(x);
    k_expert<<<NPIX/TILE, 256, smem_expert>>>(x, ew1, eb1, ew2, eb2, out);
    k_aux<<<1, 128>>>(proto, out, out_size);
}

// round 2
// speedup vs baseline: 1.2705x; 1.2705x over previous
#include <cuda_runtime.h>
#include <math.h>

#define E    11
#define KSEL 6
#define P    64
#define NH   4
#define HD   16
#define SEQ  12
#define BB   8
#define C    128
#define HH   64
#define WW   64
#define HW   (HH*WW)        /* 4096  */
#define NPIX (BB*HW)        /* 32768 */
#define HID  512
#define TILE 32
#define HPAD 20             /* hs row stride (floats): 16B-aligned, conflict-free STS.128 */
#define APAD 33             /* acc row stride: de-conflicts smem atomics */

// ---------------- device scratch (no allocation allowed) ----------------
__device__ float g_gc[BB*C];
__device__ float g_up[BB*E*P];
__device__ float g_Wr[BB*E*C];
__device__ float g_br[BB*E];
__device__ float g_route[E*NPIX];
__device__ float g_probsum[E];
__device__ float g_loadsum[E];
__device__ float g_w1t[E*C*HID];   // [e][c][r]  (transposed W1)
__device__ float g_w2t[E*HID*C];   // [e][j][c]  (transposed W2)

// ---------------- transpose: dst[e][c][r] = src[e][r][c] ------------------
__global__ void k_tr(const float* __restrict__ src, int which, int R, int Cc) {
    __shared__ float t[32][33];
    int e  = blockIdx.z;
    int r0 = blockIdx.y * 32;
    int c0 = blockIdx.x * 32;
    const float* s = src + (size_t)e * R * Cc;
    float* d = (which ? g_w2t : g_w1t) + (size_t)e * R * Cc;
    int tx = threadIdx.x & 31, ty = threadIdx.x >> 5;
    #pragma unroll
    for (int i = 0; i < 32; i += 8)
        t[ty + i][tx] = s[(size_t)(r0 + ty + i) * Cc + c0 + tx];
    __syncthreads();
    #pragma unroll
    for (int i = 0; i < 32; i += 8)
        d[(size_t)(c0 + ty + i) * R + r0 + tx] = t[tx][ty + i];
}

// ---------------- kernel 0: global-context means + zero accumulators ----
__global__ void k_gc(const float* __restrict__ x) {
    int bc = blockIdx.x;                       // 0..B*C-1
    const float4* src = reinterpret_cast<const float4*>(x + (size_t)bc * HW);
    float s = 0.f;
    for (int i = threadIdx.x; i < HW/4; i += 128) {
        float4 v = src[i];
        s += v.x + v.y + v.z + v.w;
    }
    __shared__ float red[4];
    for (int o = 16; o; o >>= 1) s += __shfl_down_sync(0xffffffffu, s, o);
    if ((threadIdx.x & 31) == 0) red[threadIdx.x >> 5] = s;
    __syncthreads();
    if (threadIdx.x == 0) {
        float t = red[0] + red[1] + red[2] + red[3];
        g_gc[bc] = t * (1.0f / HW);
    }
    if (bc == 0 && threadIdx.x < E) {
        g_probsum[threadIdx.x] = 0.f;
        g_loadsum[threadIdx.x] = 0.f;
    }
}

// ---------------- kernel A: attention path + router weight folding ------
__global__ void k_attn(const float* __restrict__ proto,
                       const float* __restrict__ ctx_w, const float* __restrict__ ctx_b,
                       const float* __restrict__ inp_w, const float* __restrict__ inp_b,
                       const float* __restrict__ wq, const float* __restrict__ bq,
                       const float* __restrict__ wk, const float* __restrict__ bk,
                       const float* __restrict__ wv, const float* __restrict__ bv,
                       const float* __restrict__ wo, const float* __restrict__ bo,
                       const float* __restrict__ ln_g, const float* __restrict__ ln_b) {
    int b = blockIdx.x;
    int t = threadIdx.x;                       // 64 threads
    __shared__ float seq[SEQ][P], qs[SEQ][P], ks[SEQ][P], vs[SEQ][P], ao[SEQ][P], o2[SEQ][P];
    __shared__ float gx[C];
    __shared__ float mstat[SEQ], istat[SEQ];

    for (int c = t; c < C; c += 64) gx[c] = g_gc[b*C + c];
    __syncthreads();

    { // gc projection -> seq[0]
        float a = ctx_b[t];
        for (int c = 0; c < C; c++) a += gx[c] * ctx_w[t*C + c];
        seq[0][t] = a;
    }
    for (int s = 1; s < SEQ; s++) seq[s][t] = proto[(s-1)*P + t];
    __syncthreads();

    for (int s = 0; s < SEQ; s++) {
        float aq = bq[t], ak = bk[t], av = bv[t];
        for (int p = 0; p < P; p++) {
            float sv = seq[s][p];
            aq += sv * wq[t*P + p];
            ak += sv * wk[t*P + p];
            av += sv * wv[t*P + p];
        }
        qs[s][t] = aq; ks[s][t] = ak; vs[s][t] = av;
    }
    __syncthreads();

    if (t < NH*SEQ) {                          // one (head, query) per thread
        int n = t / SEQ, i = t % SEQ;
        float sc[SEQ];
        float mx = -1e30f;
        for (int j = 0; j < SEQ; j++) {
            float a = 0.f;
            for (int d = 0; d < HD; d++) a += qs[i][n*HD + d] * ks[j][n*HD + d];
            a *= 0.25f;                        // 1/sqrt(HD)
            sc[j] = a; mx = fmaxf(mx, a);
        }
        float sm = 0.f;
        for (int j = 0; j < SEQ; j++) { sc[j] = expf(sc[j] - mx); sm += sc[j]; }
        float inv = 1.0f / sm;
        for (int d = 0; d < HD; d++) {
            float a = 0.f;
            for (int j = 0; j < SEQ; j++) a += sc[j] * vs[j][n*HD + d];
            ao[i][n*HD + d] = a * inv;
        }
    }
    __syncthreads();

    for (int s = 0; s < SEQ; s++) {
        float a = bo[t];
        for (int p = 0; p < P; p++) a += ao[s][p] * wo[t*P + p];
        o2[s][t] = a + seq[s][t];              // residual
    }
    __syncthreads();

    if (t < SEQ) {
        float m = 0.f;
        for (int p = 0; p < P; p++) m += o2[t][p];
        m *= (1.0f / P);
        float v = 0.f;
        for (int p = 0; p < P; p++) { float d = o2[t][p] - m; v += d*d; }
        v *= (1.0f / P);
        mstat[t] = m; istat[t] = 1.0f / sqrtf(v + 1e-5f);
    }
    __syncthreads();

    for (int s = 1; s < SEQ; s++) {
        float val = (o2[s][t] - mstat[s]) * istat[s] * ln_g[t] + ln_b[t];
        g_up[(b*E + (s-1))*P + t] = val;
        seq[s][t] = val;                       // reuse smem as "up"
    }
    __syncthreads();

    // fold inp_w into per-(b,e) router vectors: Wr[e][c] = sum_p up[e][p]*inp_w[p][c]
    for (int idx = t; idx < E*C; idx += 64) {
        int e = idx / C, c = idx % C;
        float a = 0.f;
        for (int p = 0; p < P; p++) a += seq[e+1][p] * inp_w[p*C + c];
        g_Wr[(b*E + e)*C + c] = a;
    }
    if (t < E) {
        float a = 0.f;
        for (int p = 0; p < P; p++) a += seq[t+1][p] * inp_b[p];
        g_br[b*E + t] = a;
    }
}

// ---------------- kernel B: routing (softmax + top-6) per pixel ---------
__global__ void k_route(const float* __restrict__ x) {
    int pix = blockIdx.x * 256 + threadIdx.x;  // 32768
    int b = pix / HW;
    __shared__ float wr[E*C];
    __shared__ float br[E];
    __shared__ float psum[E], lsum[E];
    for (int i = threadIdx.x; i < E*C; i += 256) wr[i] = g_Wr[b*E*C + i];
    if (threadIdx.x < E) {
        br[threadIdx.x] = g_br[b*E + threadIdx.x];
        psum[threadIdx.x] = 0.f; lsum[threadIdx.x] = 0.f;
    }
    __syncthreads();

    float pr[E];
    #pragma unroll
    for (int e = 0; e < E; e++) pr[e] = br[e];
    const float* xp = x + (size_t)b*C*HW + (pix - b*HW);
    for (int c = 0; c < C; c++) {
        float xv = xp[(size_t)c * HW];
        #pragma unroll
        for (int e = 0; e < E; e++) pr[e] += xv * wr[e*C + c];
    }
    float mx = -1e30f;
    #pragma unroll
    for (int e = 0; e < E; e++) { pr[e] *= 0.125f; mx = fmaxf(mx, pr[e]); }
    float sm = 0.f;
    #pragma unroll
    for (int e = 0; e < E; e++) { pr[e] = expf(pr[e] - mx); sm += pr[e]; }
    float invs = 1.0f / sm;
    #pragma unroll
    for (int e = 0; e < E; e++) pr[e] *= invs;     // probs

    // top-6 (first index wins ties, matching lax.top_k)
    int used = 0;
    float tsum = 0.f;
    #pragma unroll
    for (int k2 = 0; k2 < KSEL; k2++) {
        float bv = -1.f; int bi = 0;
        #pragma unroll
        for (int e = 0; e < E; e++)
            if (!((used >> e) & 1) && pr[e] > bv) { bv = pr[e]; bi = e; }
        used |= 1 << bi;
        tsum += bv;
    }
    float invt = 1.0f / tsum;
    #pragma unroll
    for (int e = 0; e < E; e++) {
        int selq = (used >> e) & 1;
        g_route[(size_t)e * NPIX + pix] = selq ? pr[e] * invt : 0.f;
        atomicAdd(&psum[e], pr[e]);
        if (selq) atomicAdd(&lsum[e], 1.f);
    }
    __syncthreads();
    if (threadIdx.x < E) {
        atomicAdd(&g_probsum[threadIdx.x], psum[threadIdx.x]);
        atomicAdd(&g_loadsum[threadIdx.x], lsum[threadIdx.x]);
    }
}

// ---------------- kernel C: sparse expert MLPs ---------------------------
// phase 1: 2 rows x 16 px per thread; phase 2: 2 channels x 16 px per thread,
// j split 4-way, reduced via padded smem atomics. Weights read coalesced
// from pre-transposed g_w1t/g_w2t.
__global__ void __launch_bounds__(256, 2)
k_expert(const float* __restrict__ x,
         const float* __restrict__ eb1,
         const float* __restrict__ eb2,
         float* __restrict__ out) {
    extern __shared__ float smem[];
    float* xs   = smem;                 // [C][TILE]     4096 f
    float* xsel = xs   + C*TILE;        // [C][TILE]     4096 f
    float* acc  = xsel + C*TILE;        // [C][APAD]     4224 f
    float* hs   = acc  + C*APAD;        // [HID][HPAD]  10240 f
    __shared__ int   sel[TILE];
    __shared__ float wt[TILE];
    __shared__ int   mcnt;

    const int tid  = threadIdx.x;
    const int pix0 = blockIdx.x * TILE;
    const int b    = pix0 / HW;
    const int off  = pix0 - b*HW;
    const float* xb = x + (size_t)b*C*HW + off;

    for (int idx = tid; idx < C*TILE; idx += 256) {
        int c = idx >> 5, i = idx & 31;
        xs[idx] = xb[(size_t)c * HW + i];
    }
    for (int idx = tid; idx < C*APAD; idx += 256) acc[idx] = 0.f;

    const int cpair = tid & 63;
    const int c0    = cpair * 2;
    const int jsl   = tid >> 6;                // 0..3

    for (int e = 0; e < E; e++) {
        __syncthreads();                       // protect sel/wt/xsel/hs reuse
        if (tid == 0) {
            int m = 0;
            #pragma unroll
            for (int i = 0; i < TILE; i++) {
                float w = g_route[(size_t)e * NPIX + pix0 + i];
                if (w > 0.f) { sel[m] = i; wt[m] = w; m++; }
            }
            int mpad = (m + 7) & ~7;
            for (int i = m; i < mpad; i++) { sel[i] = 0; wt[i] = 0.f; }
            mcnt = m;
        }
        __syncthreads();
        const int m = mcnt;
        if (m == 0) continue;
        const int mp  = (m + 7) & ~7;
        const int G   = mp >> 3;               // 1..4 groups of 8 px
        const int nch = (G + 1) >> 1;          // chunks of up to 16 px

        // compact selected pixels: xsel[c][s] = xs[c][sel[s]]
        for (int idx = tid; idx < C*TILE; idx += 256) {
            int s2 = idx & 31;
            if (s2 < mp) xsel[idx] = xs[(idx & ~31) + sel[s2]];
        }

        const float* w1e = g_w1t + (size_t)e * C * HID;
        const float* w2e = g_w2t + (size_t)e * HID * C;

        for (int ch = 0; ch < nch; ch++) {
            const int g0 = ch * 2;
            const int Gc = min(G - g0, 2);     // 1 or 2 groups this chunk
            __syncthreads();                   // xsel ready / hs free

            // ---- phase 1: h = gelu(W1 x + b1); rows tid, tid+256 ----
            {
                float a0[16], a1[16];
                #pragma unroll
                for (int i = 0; i < 16; i++) { a0[i] = 0.f; a1[i] = 0.f; }
                #pragma unroll 2
                for (int c = 0; c < C; c++) {
                    float w0 = w1e[(size_t)c*HID + tid];
                    float w1 = w1e[(size_t)c*HID + 256 + tid];
                    const float4* xv = reinterpret_cast<const float4*>(xsel + c*TILE) + g0*2;
                    #pragma unroll
                    for (int g = 0; g < 2; g++) {
                        if (g < Gc) {
                            float4 u0 = xv[2*g], u1 = xv[2*g+1];
                            a0[g*8+0] += w0*u0.x; a0[g*8+1] += w0*u0.y;
                            a0[g*8+2] += w0*u0.z; a0[g*8+3] += w0*u0.w;
                            a0[g*8+4] += w0*u1.x; a0[g*8+5] += w0*u1.y;
                            a0[g*8+6] += w0*u1.z; a0[g*8+7] += w0*u1.w;
                            a1[g*8+0] += w1*u0.x; a1[g*8+1] += w1*u0.y;
                            a1[g*8+2] += w1*u0.z; a1[g*8+3] += w1*u0.w;
                            a1[g*8+4] += w1*u1.x; a1[g*8+5] += w1*u1.y;
                            a1[g*8+6] += w1*u1.z; a1[g*8+7] += w1*u1.w;
                        }
                    }
                }
                float b10 = eb1[(size_t)e*HID + tid];
                float b11 = eb1[(size_t)e*HID + 256 + tid];
                #pragma unroll
                for (int s = 0; s < 16; s++) {
                    if (s < 8*Gc) {
                        float v0 = a0[s] + b10;
                        float v1 = a1[s] + b11;
                        hs[tid*HPAD + s]         = 0.5f*v0*(1.0f + erff(v0*0.70710678118654752f));
                        hs[(tid+256)*HPAD + s]   = 0.5f*v1*(1.0f + erff(v1*0.70710678118654752f));
                    }
                }
            }
            __syncthreads();                   // hs ready

            // ---- phase 2: y = W2 h; channels c0,c0+1; j-slice jsl ----
            {
                float y0[16], y1[16];
                #pragma unroll
                for (int i = 0; i < 16; i++) { y0[i] = 0.f; y1[i] = 0.f; }
                #pragma unroll 2
                for (int jj = 0; jj < HID/4; jj++) {
                    int j = jsl*(HID/4) + jj;
                    float2 w = *reinterpret_cast<const float2*>(w2e + (size_t)j*C + c0);
                    const float4* hv = reinterpret_cast<const float4*>(hs + j*HPAD);
                    #pragma unroll
                    for (int g = 0; g < 2; g++) {
                        if (g < Gc) {
                            float4 u0 = hv[2*g], u1 = hv[2*g+1];
                            y0[g*8+0] += w.x*u0.x; y0[g*8+1] += w.x*u0.y;
                            y0[g*8+2] += w.x*u0.z; y0[g*8+3] += w.x*u0.w;
                            y0[g*8+4] += w.x*u1.x; y0[g*8+5] += w.x*u1.y;
                            y0[g*8+6] += w.x*u1.z; y0[g*8+7] += w.x*u1.w;
                            y1[g*8+0] += w.y*u0.x; y1[g*8+1] += w.y*u0.y;
                            y1[g*8+2] += w.y*u0.z; y1[g*8+3] += w.y*u0.w;
                            y1[g*8+4] += w.y*u1.x; y1[g*8+5] += w.y*u1.y;
                            y1[g*8+6] += w.y*u1.z; y1[g*8+7] += w.y*u1.w;
                        }
                    }
                }
                float b20 = (jsl == 0) ? eb2[(size_t)e*C + c0]     : 0.f;
                float b21 = (jsl == 0) ? eb2[(size_t)e*C + c0 + 1] : 0.f;
                #pragma unroll
                for (int s = 0; s < 16; s++) {
                    if (s < 8*Gc) {
                        int   si  = 16*ch + s;
                        float wts = wt[si];
                        int   px  = sel[si];
                        atomicAdd(&acc[c0*APAD + px],     wts * (y0[s] + b20));
                        atomicAdd(&acc[(c0+1)*APAD + px], wts * (y1[s] + b21));
                    }
                }
            }
        } // chunks
    } // experts
    __syncthreads();

    float* ob = out + (size_t)b*C*HW + off;
    for (int idx = tid; idx < C*TILE; idx += 256) {
        int c = idx >> 5, i = idx & 31;
        ob[(size_t)c * HW + i] = xs[idx] + acc[c*APAD + i];
    }
}

// ---------------- kernel D: aux scalar -----------------------------------
__global__ void k_aux(const float* __restrict__ proto, float* __restrict__ out, int out_size) {
    __shared__ float pn[E][P];
    __shared__ float red[128];
    int t = threadIdx.x;                       // 128 threads
    if (t < E) {
        float s = 0.f;
        for (int p = 0; p < P; p++) { float v = proto[t*P + p]; s += v*v; }
        float inv = 1.0f / sqrtf(s);
        for (int p = 0; p < P; p++) pn[t][p] = proto[t*P + p] * inv;
    }
    __syncthreads();
    float s = 0.f;
    for (int idx = t; idx < E*E; idx += 128) {
        int i = idx / E, j = idx % E;
        float d = 0.f;
        for (int p = 0; p < P; p++) d += pn[i][p] * pn[j][p];
        d -= (i == j) ? 1.0f : 0.0f;
        s += d*d;
    }
    red[t] = s;
    __syncthreads();
    for (int st = 64; st; st >>= 1) { if (t < st) red[t] += red[t + st]; __syncthreads(); }
    if (t == 0) {
        float ortho = sqrtf(red[0]);
        float aux = 0.f;
        for (int e = 0; e < E; e++)
            aux += (g_probsum[e] * (1.0f/NPIX)) * (g_loadsum[e] * (1.0f/NPIX));
        aux *= (float)E;
        if (out_size > BB*C*HW) out[BB*C*HW] = aux + 0.5f * ortho;
    }
}

// ---------------- launcher ------------------------------------------------
extern "C" void kernel_launch(void* const* d_in, const int* in_sizes, int n_in,
                              void* d_out, int out_size) {
    const float* x      = (const float*)d_in[0];
    const float* proto  = (const float*)d_in[1];
    const float* ctx_w  = (const float*)d_in[2];
    const float* ctx_b  = (const float*)d_in[3];
    const float* inp_w  = (const float*)d_in[4];
    const float* inp_b  = (const float*)d_in[5];
    const float* wq     = (const float*)d_in[6];
    const float* bq     = (const float*)d_in[7];
    const float* wk     = (const float*)d_in[8];
    const float* bk     = (const float*)d_in[9];
    const float* wv     = (const float*)d_in[10];
    const float* bv     = (const float*)d_in[11];
    const float* wo     = (const float*)d_in[12];
    const float* bo     = (const float*)d_in[13];
    const float* ln_g   = (const float*)d_in[14];
    const float* ln_b   = (const float*)d_in[15];
    const float* ew1    = (const float*)d_in[16];
    const float* eb1    = (const float*)d_in[17];
    const float* ew2    = (const float*)d_in[18];
    const float* eb2    = (const float*)d_in[19];
    float* out = (float*)d_out;

    const int smem_expert = (3*C*TILE + C*(APAD-TILE) + HID*HPAD) * (int)sizeof(float); // 90624 B
    cudaFuncSetAttribute(k_expert, cudaFuncAttributeMaxDynamicSharedMemorySize, smem_expert);

    k_tr<<<dim3(C/32,  HID/32, E), 256>>>(ew1, 0, HID, C);   // g_w1t[e][c][r]
    k_tr<<<dim3(HID/32, C/32,  E), 256>>>(ew2, 1, C, HID);   // g_w2t[e][j][c]
    k_gc<<<BB*C, 128>>>(x);
    k_attn<<<BB, 64>>>(proto, ctx_w, ctx_b, inp_w, inp_b,
                       wq, bq, wk, bk, wv, bv, wo, bo, ln_g, ln_b);
    k_route<<<NPIX/256, 256>>>(x);
    k_expert<<<NPIX/TILE, 256, smem_expert>>>(x, eb1, eb2, out);
    k_aux<<<1, 128>>>(proto, out, out_size);
}

// round 3
// speedup vs baseline: 2.5146x; 1.9792x over previous
#include <cuda_runtime.h>
#include <math.h>

#define E    11
#define KSEL 6
#define P    64
#define NH   4
#define HD   16
#define SEQ  12
#define BB   8
#define C    128
#define HH   64
#define WW   64
#define HW   (HH*WW)        /* 4096  */
#define NPIX (BB*HW)        /* 32768 */
#define HID  512
#define SPAD 132            /* smem row stride (floats) for k_mlp tiles */

// ---------------- device scratch (no allocation allowed) ----------------
__device__ float g_gc[BB*C];
__device__ float g_Wr[BB*E*C];
__device__ float g_br[BB*E];
__device__ float g_route[E*NPIX];
__device__ float g_probsum[E];
__device__ float g_loadsum[E];
__device__ float g_w1t[E*C*HID];   // [e][c][r]  (transposed W1)
__device__ float g_w2t[E*HID*C];   // [e][j][c]  (transposed W2)
__device__ int   g_cnt[E];
__device__ int   g_pidx[E*NPIX];   // [e][slot] -> pixel
__device__ int   g_slot[E*NPIX];   // [e][pixel] -> slot (valid only if selected)
__device__ float g_ybuf[E*NPIX*C]; // [e][slot][c]  expert outputs (pre-weight)

// ---------------- transpose: dst[e][c][r] = src[e][r][c] ------------------
__global__ void k_tr(const float* __restrict__ src, int which, int R, int Cc) {
    __shared__ float t[32][33];
    int e  = blockIdx.z;
    int r0 = blockIdx.y * 32;
    int c0 = blockIdx.x * 32;
    const float* s = src + (size_t)e * R * Cc;
    float* d = (which ? g_w2t : g_w1t) + (size_t)e * R * Cc;
    int tx = threadIdx.x & 31, ty = threadIdx.x >> 5;
    #pragma unroll
    for (int i = 0; i < 32; i += 8)
        t[ty + i][tx] = s[(size_t)(r0 + ty + i) * Cc + c0 + tx];
    __syncthreads();
    #pragma unroll
    for (int i = 0; i < 32; i += 8)
        d[(size_t)(c0 + ty + i) * R + r0 + tx] = t[tx][ty + i];
}

// ---------------- kernel 0: global-context means + zero counters --------
__global__ void k_gc(const float* __restrict__ x) {
    int bc = blockIdx.x;                       // 0..B*C-1
    const float4* src = reinterpret_cast<const float4*>(x + (size_t)bc * HW);
    float s = 0.f;
    for (int i = threadIdx.x; i < HW/4; i += 128) {
        float4 v = src[i];
        s += v.x + v.y + v.z + v.w;
    }
    __shared__ float red[4];
    for (int o = 16; o; o >>= 1) s += __shfl_down_sync(0xffffffffu, s, o);
    if ((threadIdx.x & 31) == 0) red[threadIdx.x >> 5] = s;
    __syncthreads();
    if (threadIdx.x == 0) {
        float t = red[0] + red[1] + red[2] + red[3];
        g_gc[bc] = t * (1.0f / HW);
    }
    if (bc == 0 && threadIdx.x < E) {
        g_probsum[threadIdx.x] = 0.f;
        g_loadsum[threadIdx.x] = 0.f;
        g_cnt[threadIdx.x] = 0;
    }
}

// ---------------- kernel A: attention path + router weight folding ------
__global__ void k_attn(const float* __restrict__ proto,
                       const float* __restrict__ ctx_w, const float* __restrict__ ctx_b,
                       const float* __restrict__ inp_w, const float* __restrict__ inp_b,
                       const float* __restrict__ wq, const float* __restrict__ bq,
                       const float* __restrict__ wk, const float* __restrict__ bk,
                       const float* __restrict__ wv, const float* __restrict__ bv,
                       const float* __restrict__ wo, const float* __restrict__ bo,
                       const float* __restrict__ ln_g, const float* __restrict__ ln_b) {
    int b = blockIdx.x;
    int t = threadIdx.x;                       // 256 threads
    __shared__ float seq[SEQ][P], qs[SEQ][P], ks[SEQ][P], vs[SEQ][P], ao[SEQ][P], o2[SEQ][P];
    __shared__ float gx[C];
    __shared__ float mstat[SEQ], istat[SEQ];

    if (t < C) gx[t] = g_gc[b*C + t];
    __syncthreads();

    if (t < P) {                               // gc projection -> seq[0]
        float a = ctx_b[t];
        for (int c = 0; c < C; c++) a += gx[c] * ctx_w[t*C + c];
        seq[0][t] = a;
    }
    for (int z = t; z < E*P; z += 256) seq[1 + z/P][z%P] = proto[z];
    __syncthreads();

    for (int z = t; z < SEQ*P; z += 256) {     // QKV
        int s = z >> 6, p = z & 63;
        float aq = bq[p], ak = bk[p], av = bv[p];
        for (int q = 0; q < P; q++) {
            float sv = seq[s][q];
            aq += sv * wq[p*P + q];
            ak += sv * wk[p*P + q];
            av += sv * wv[p*P + q];
        }
        qs[s][p] = aq; ks[s][p] = ak; vs[s][p] = av;
    }
    __syncthreads();

    if (t < NH*SEQ) {                          // one (head, query) per thread
        int n = t / SEQ, i = t % SEQ;
        float sc[SEQ];
        float mx = -1e30f;
        for (int j = 0; j < SEQ; j++) {
            float a = 0.f;
            for (int d = 0; d < HD; d++) a += qs[i][n*HD + d] * ks[j][n*HD + d];
            a *= 0.25f;                        // 1/sqrt(HD)
            sc[j] = a; mx = fmaxf(mx, a);
        }
        float sm = 0.f;
        for (int j = 0; j < SEQ; j++) { sc[j] = expf(sc[j] - mx); sm += sc[j]; }
        float inv = 1.0f / sm;
        for (int d = 0; d < HD; d++) {
            float a = 0.f;
            for (int j = 0; j < SEQ; j++) a += sc[j] * vs[j][n*HD + d];
            ao[i][n*HD + d] = a * inv;
        }
    }
    __syncthreads();

    for (int z = t; z < SEQ*P; z += 256) {     // output proj + residual
        int s = z >> 6, p = z & 63;
        float a = bo[p];
        for (int q = 0; q < P; q++) a += ao[s][q] * wo[p*P + q];
        o2[s][p] = a + seq[s][p];
    }
    __syncthreads();

    if (t < SEQ) {
        float m = 0.f;
        for (int p = 0; p < P; p++) m += o2[t][p];
        m *= (1.0f / P);
        float v = 0.f;
        for (int p = 0; p < P; p++) { float d = o2[t][p] - m; v += d*d; }
        v *= (1.0f / P);
        mstat[t] = m; istat[t] = 1.0f / sqrtf(v + 1e-5f);
    }
    __syncthreads();

    for (int z = t; z < E*P; z += 256) {       // layernorm -> "up" (reuse seq rows 1..11)
        int s = z / P + 1, p = z % P;
        seq[s][p] = (o2[s][p] - mstat[s]) * istat[s] * ln_g[p] + ln_b[p];
    }
    __syncthreads();

    // fold inp_w: Wr[e][c] = sum_p up[e][p]*inp_w[p][c]
    for (int z = t; z < E*C; z += 256) {
        int e = z / C, c = z % C;
        float a = 0.f;
        for (int p = 0; p < P; p++) a += seq[e+1][p] * inp_w[p*C + c];
        g_Wr[(b*E + e)*C + c] = a;
    }
    if (t < E) {
        float a = 0.f;
        for (int p = 0; p < P; p++) a += seq[t+1][p] * inp_b[p];
        g_br[b*E + t] = a;
    }
}

// ---------------- kernel B: routing + per-expert compaction -------------
__global__ void k_route(const float* __restrict__ x) {
    int pix = blockIdx.x * 256 + threadIdx.x;  // 32768
    int b = pix / HW;
    __shared__ float wr[E*C];
    __shared__ float br[E];
    __shared__ float psum[E], lsum[E];
    __shared__ int   scnt[E], sbase[E];
    for (int i = threadIdx.x; i < E*C; i += 256) wr[i] = g_Wr[b*E*C + i];
    if (threadIdx.x < E) {
        br[threadIdx.x] = g_br[b*E + threadIdx.x];
        psum[threadIdx.x] = 0.f; lsum[threadIdx.x] = 0.f;
        scnt[threadIdx.x] = 0;
    }
    __syncthreads();

    float pr[E];
    #pragma unroll
    for (int e = 0; e < E; e++) pr[e] = br[e];
    const float* xp = x + (size_t)b*C*HW + (pix - b*HW);
    for (int c = 0; c < C; c++) {
        float xv = xp[(size_t)c * HW];
        #pragma unroll
        for (int e = 0; e < E; e++) pr[e] += xv * wr[e*C + c];
    }
    float mx = -1e30f;
    #pragma unroll
    for (int e = 0; e < E; e++) { pr[e] *= 0.125f; mx = fmaxf(mx, pr[e]); }
    float sm = 0.f;
    #pragma unroll
    for (int e = 0; e < E; e++) { pr[e] = expf(pr[e] - mx); sm += pr[e]; }
    float invs = 1.0f / sm;
    #pragma unroll
    for (int e = 0; e < E; e++) pr[e] *= invs;     // probs

    // top-6 (first index wins ties, matching lax.top_k)
    int used = 0;
    float tsum = 0.f;
    #pragma unroll
    for (int k2 = 0; k2 < KSEL; k2++) {
        float bv = -1.f; int bi = 0;
        #pragma unroll
        for (int e = 0; e < E; e++)
            if (!((used >> e) & 1) && pr[e] > bv) { bv = pr[e]; bi = e; }
        used |= 1 << bi;
        tsum += bv;
    }
    float invt = 1.0f / tsum;

    int loc[E];
    #pragma unroll
    for (int e = 0; e < E; e++) {
        int selq = (used >> e) & 1;
        g_route[(size_t)e * NPIX + pix] = selq ? pr[e] * invt : 0.f;
        atomicAdd(&psum[e], pr[e]);
        loc[e] = selq ? atomicAdd(&scnt[e], 1) : -1;
    }
    __syncthreads();
    if (threadIdx.x < E) {
        int e = threadIdx.x;
        sbase[e] = atomicAdd(&g_cnt[e], scnt[e]);
        atomicAdd(&g_probsum[e], psum[e]);
        atomicAdd(&g_loadsum[e], (float)scnt[e]);
    }
    __syncthreads();
    #pragma unroll
    for (int e = 0; e < E; e++) {
        if (loc[e] >= 0) {
            int slot = sbase[e] + loc[e];
            g_pidx[e*NPIX + slot] = pix;
            g_slot[e*NPIX + pix]  = slot;
        }
    }
}

// ---------------- kernel C: grouped-GEMM expert MLPs --------------------
// block = (expert e = blockIdx.y, 128-pixel tile = blockIdx.x), 256 threads.
// GEMM1: H = gelu(X @ W1 + b1) in 4 chunks of 128 hidden; GEMM2: Y += H @ W2.
// thread tile: 8 px x 8 out; GEMM1 r-dim strided (r = jj*16 + tr).
__global__ void __launch_bounds__(256, 1)
k_mlp(const float* __restrict__ x,
      const float* __restrict__ eb1,
      const float* __restrict__ eb2) {
    extern __shared__ float smem[];
    float* Xs = smem;                  // [128 c][SPAD]  (px in row)
    float* Ws = Xs + C*SPAD;           // [128 k][SPAD]
    float* Hs = Ws + C*SPAD;           // [128 j][SPAD]
    __shared__ int pid[128];

    const int e = blockIdx.y;
    const int cnt = g_cnt[e];
    const int tile0 = blockIdx.x * 128;
    if (tile0 >= cnt) return;
    const int rem = min(128, cnt - tile0);
    const int t = threadIdx.x;

    if (t < 128) pid[t] = g_pidx[e*NPIX + tile0 + min(t, rem - 1)];
    __syncthreads();

    // gather X: Xs[c][px]
    for (int idx = t; idx < C*128; idx += 256) {
        int px = idx & 127, c = idx >> 7;
        int p = pid[px];
        int b = p >> 12;
        Xs[c*SPAD + px] = x[(size_t)b*(C-1)*HW + (size_t)c*HW + p];
    }

    const float* w1e = g_w1t + (size_t)e * C * HID;
    const float* w2e = g_w2t + (size_t)e * HID * C;

    const int tr  = t & 15;            // 0..15
    const int tp  = t >> 4;            // 0..15
    const int px0 = tp * 8;
    const int c0t = tr * 8;

    float yacc[64];
    #pragma unroll
    for (int i = 0; i < 64; i++) yacc[i] = 0.f;

    for (int rc = 0; rc < 4; rc++) {
        const int r0 = rc * 128;
        __syncthreads();                       // Ws free (prev GEMM2 done / gather done)
        for (int idx = t; idx < 128*128; idx += 256) {
            int rr = idx & 127, c = idx >> 7;
            Ws[c*SPAD + rr] = w1e[(size_t)c*HID + r0 + rr];
        }
        __syncthreads();

        // ---- GEMM1: h[px i][r jj],  r = jj*16 + tr
        float h[64];
        #pragma unroll
        for (int i = 0; i < 64; i++) h[i] = 0.f;
        #pragma unroll 2
        for (int k = 0; k < 128; k++) {
            float4 a0 = *reinterpret_cast<const float4*>(Xs + k*SPAD + px0);
            float4 a1 = *reinterpret_cast<const float4*>(Xs + k*SPAD + px0 + 4);
            float bv[8];
            #pragma unroll
            for (int jj = 0; jj < 8; jj++) bv[jj] = Ws[k*SPAD + jj*16 + tr];
            #pragma unroll
            for (int jj = 0; jj < 8; jj++) {
                h[0*8+jj] += a0.x*bv[jj]; h[1*8+jj] += a0.y*bv[jj];
                h[2*8+jj] += a0.z*bv[jj]; h[3*8+jj] += a0.w*bv[jj];
                h[4*8+jj] += a1.x*bv[jj]; h[5*8+jj] += a1.y*bv[jj];
                h[6*8+jj] += a1.z*bv[jj]; h[7*8+jj] += a1.w*bv[jj];
            }
        }
        // gelu + bias -> Hs[r][px]
        #pragma unroll
        for (int jj = 0; jj < 8; jj++) {
            float b1 = eb1[(size_t)e*HID + r0 + jj*16 + tr];
            float4 v0, v1;
            {
                float u;
                u = h[0*8+jj] + b1; v0.x = 0.5f*u*(1.0f + erff(u*0.70710678118654752f));
                u = h[1*8+jj] + b1; v0.y = 0.5f*u*(1.0f + erff(u*0.70710678118654752f));
                u = h[2*8+jj] + b1; v0.z = 0.5f*u*(1.0f + erff(u*0.70710678118654752f));
                u = h[3*8+jj] + b1; v0.w = 0.5f*u*(1.0f + erff(u*0.70710678118654752f));
                u = h[4*8+jj] + b1; v1.x = 0.5f*u*(1.0f + erff(u*0.70710678118654752f));
                u = h[5*8+jj] + b1; v1.y = 0.5f*u*(1.0f + erff(u*0.70710678118654752f));
                u = h[6*8+jj] + b1; v1.z = 0.5f*u*(1.0f + erff(u*0.70710678118654752f));
                u = h[7*8+jj] + b1; v1.w = 0.5f*u*(1.0f + erff(u*0.70710678118654752f));
            }
            *reinterpret_cast<float4*>(Hs + (jj*16 + tr)*SPAD + px0)     = v0;
            *reinterpret_cast<float4*>(Hs + (jj*16 + tr)*SPAD + px0 + 4) = v1;
        }
        __syncthreads();                       // Hs ready; Ws reads (GEMM1) all done
        // load W2 chunk: Ws[j][c]
        for (int idx = t; idx < 128*128; idx += 256) {
            int cc = idx & 127, j = idx >> 7;
            Ws[j*SPAD + cc] = w2e[(size_t)(r0 + j)*C + cc];
        }
        __syncthreads();

        // ---- GEMM2: yacc[px i][c q], c = c0t + q
        #pragma unroll 2
        for (int k = 0; k < 128; k++) {
            float4 a0 = *reinterpret_cast<const float4*>(Hs + k*SPAD + px0);
            float4 a1 = *reinterpret_cast<const float4*>(Hs + k*SPAD + px0 + 4);
            float4 b0 = *reinterpret_cast<const float4*>(Ws + k*SPAD + c0t);
            float4 b1 = *reinterpret_cast<const float4*>(Ws + k*SPAD + c0t + 4);
            #pragma unroll
            for (int i = 0; i < 8; i++) {
                float av = (i==0)?a0.x:(i==1)?a0.y:(i==2)?a0.z:(i==3)?a0.w:
                           (i==4)?a1.x:(i==5)?a1.y:(i==6)?a1.z:a1.w;
                yacc[i*8+0] += av*b0.x; yacc[i*8+1] += av*b0.y;
                yacc[i*8+2] += av*b0.z; yacc[i*8+3] += av*b0.w;
                yacc[i*8+4] += av*b1.x; yacc[i*8+5] += av*b1.y;
                yacc[i*8+6] += av*b1.z; yacc[i*8+7] += av*b1.w;
            }
        }
    }

    // epilogue: + eb2, scatter rows to g_ybuf
    float bb[8];
    #pragma unroll
    for (int q = 0; q < 8; q++) bb[q] = eb2[(size_t)e*C + c0t + q];
    #pragma unroll
    for (int i = 0; i < 8; i++) {
        int sl = px0 + i;
        if (sl < rem) {
            float* dst = g_ybuf + ((size_t)e*NPIX + tile0 + sl)*C + c0t;
            float4 o0 = { yacc[i*8+0]+bb[0], yacc[i*8+1]+bb[1], yacc[i*8+2]+bb[2], yacc[i*8+3]+bb[3] };
            float4 o1 = { yacc[i*8+4]+bb[4], yacc[i*8+5]+bb[5], yacc[i*8+6]+bb[6], yacc[i*8+7]+bb[7] };
            *reinterpret_cast<float4*>(dst)     = o0;
            *reinterpret_cast<float4*>(dst + 4) = o1;
        }
    }
}

// ---------------- kernel G: weighted gather + residual ------------------
__global__ void k_gather(const float* __restrict__ x, float* __restrict__ out) {
    __shared__ float tile[C*33];               // [c][px], padded
    const int t = threadIdx.x;                 // 256
    const int lane = t & 31, w = t >> 5;       // 8 warps
    const int pix0 = blockIdx.x * 32;
    const int b = pix0 >> 12;

    #pragma unroll
    for (int k = 0; k < 4; k++) {              // each warp: 4 pixels
        int px  = w*4 + k;
        int pix = pix0 + px;
        float a0 = 0.f, a1 = 0.f, a2 = 0.f, a3 = 0.f;
        #pragma unroll
        for (int e = 0; e < E; e++) {
            float wv = g_route[(size_t)e*NPIX + pix];
            if (wv > 0.f) {
                int sl = g_slot[e*NPIX + pix];
                const float* row = g_ybuf + ((size_t)e*NPIX + sl)*C;
                a0 += wv * row[lane];
                a1 += wv * row[lane + 32];
                a2 += wv * row[lane + 64];
                a3 += wv * row[lane + 96];
            }
        }
        tile[(lane)*33 + px]      = a0;
        tile[(lane+32)*33 + px]   = a1;
        tile[(lane+64)*33 + px]   = a2;
        tile[(lane+96)*33 + px]   = a3;
    }
    __syncthreads();
    const size_t base = (size_t)b*(C-1)*HW + pix0;
    for (int idx = t; idx < C*32; idx += 256) {
        int c = idx >> 5, px = idx & 31;
        size_t a = base + (size_t)c*HW + px;
        out[a] = x[a] + tile[c*33 + px];
    }
}

// ---------------- kernel D: aux scalar -----------------------------------
__global__ void k_aux(const float* __restrict__ proto, float* __restrict__ out, int out_size) {
    __shared__ float pn[E][P];
    __shared__ float red[128];
    int t = threadIdx.x;                       // 128 threads
    if (t < E) {
        float s = 0.f;
        for (int p = 0; p < P; p++) { float v = proto[t*P + p]; s += v*v; }
        float inv = 1.0f / sqrtf(s);
        for (int p = 0; p < P; p++) pn[t][p] = proto[t*P + p] * inv;
    }
    __syncthreads();
    float s = 0.f;
    for (int idx = t; idx < E*E; idx += 128) {
        int i = idx / E, j = idx % E;
        float d = 0.f;
        for (int p = 0; p < P; p++) d += pn[i][p] * pn[j][p];
        d -= (i == j) ? 1.0f : 0.0f;
        s += d*d;
    }
    red[t] = s;
    __syncthreads();
    for (int st = 64; st; st >>= 1) { if (t < st) red[t] += red[t + st]; __syncthreads(); }
    if (t == 0) {
        float ortho = sqrtf(red[0]);
        float aux = 0.f;
        for (int e = 0; e < E; e++)
            aux += (g_probsum[e] * (1.0f/NPIX)) * (g_loadsum[e] * (1.0f/NPIX));
        aux *= (float)E;
        if (out_size > BB*C*HW) out[BB*C*HW] = aux + 0.5f * ortho;
    }
}

// ---------------- launcher ------------------------------------------------
extern "C" void kernel_launch(void* const* d_in, const int* in_sizes, int n_in,
                              void* d_out, int out_size) {
    const float* x      = (const float*)d_in[0];
    const float* proto  = (const float*)d_in[1];
    const float* ctx_w  = (const float*)d_in[2];
    const float* ctx_b  = (const float*)d_in[3];
    const float* inp_w  = (const float*)d_in[4];
    const float* inp_b  = (const float*)d_in[5];
    const float* wq     = (const float*)d_in[6];
    const float* bq     = (const float*)d_in[7];
    const float* wk     = (const float*)d_in[8];
    const float* bk     = (const float*)d_in[9];
    const float* wv     = (const float*)d_in[10];
    const float* bv     = (const float*)d_in[11];
    const float* wo     = (const float*)d_in[12];
    const float* bo     = (const float*)d_in[13];
    const float* ln_g   = (const float*)d_in[14];
    const float* ln_b   = (const float*)d_in[15];
    const float* ew1    = (const float*)d_in[16];
    const float* eb1    = (const float*)d_in[17];
    const float* ew2    = (const float*)d_in[18];
    const float* eb2    = (const float*)d_in[19];
    float* out = (float*)d_out;

    const int smem_mlp = 3 * C * SPAD * (int)sizeof(float);   // 202752 B
    cudaFuncSetAttribute(k_mlp, cudaFuncAttributeMaxDynamicSharedMemorySize, smem_mlp);

    k_tr<<<dim3(C/32,  HID/32, E), 256>>>(ew1, 0, HID, C);   // g_w1t[e][c][r]
    k_tr<<<dim3(HID/32, C/32,  E), 256>>>(ew2, 1, C, HID);   // g_w2t[e][j][c]
    k_gc<<<BB*C, 128>>>(x);
    k_attn<<<BB, 256>>>(proto, ctx_w, ctx_b, inp_w, inp_b,
                        wq, bq, wk, bk, wv, bv, wo, bo, ln_g, ln_b);
    k_route<<<NPIX/256, 256>>>(x);
    k_mlp<<<dim3(NPIX/128, E), 256, smem_mlp>>>(x, eb1, eb2);
    k_gather<<<NPIX/32, 256>>>(x, out);
    k_aux<<<1, 128>>>(proto, out, out_size);
}

// round 6
// speedup vs baseline: 5.9822x; 2.3790x over previous
#include <cuda_runtime.h>
#include <cuda_bf16.h>
#include <math.h>
#include <stdint.h>

#define E    11
#define KSEL 6
#define P    64
#define NH   4
#define HD   16
#define SEQ  12
#define BB   8
#define C    128
#define HH   64
#define WW   64
#define HW   (HH*WW)        /* 4096  */
#define NPIX (BB*HW)        /* 32768 */
#define HID  512
#define LDT  136            /* smem tile row stride in bf16 (272B = 17*16B, conflict-free) */

// ---------------- device scratch (no allocation allowed) ----------------
__device__ float g_gc[BB*C];
__device__ float g_Wr[BB*E*C];
__device__ float g_br[BB*E];
__device__ float g_route[E*NPIX];
__device__ float g_probsum[E];
__device__ float g_loadsum[E];
__device__ int   g_cnt[E];
__device__ int   g_pidx[E*NPIX];   // [e][slot] -> pixel
__device__ int   g_slot[E*NPIX];   // [e][pixel] -> slot
__device__ float g_ybuf[E*NPIX*C]; // [e][slot][c]
__device__ __align__(16) __nv_bfloat16 g_w1h[E*HID*C];  // [e][r][c] hi
__device__ __align__(16) __nv_bfloat16 g_w1l[E*HID*C];  // [e][r][c] lo
__device__ __align__(16) __nv_bfloat16 g_w2h[E*C*HID];  // [e][c][j] hi
__device__ __align__(16) __nv_bfloat16 g_w2l[E*C*HID];  // [e][c][j] lo

// ---------------- mma/ldmatrix helpers (sm_80-era, no 'a' gating) --------
__device__ __forceinline__ uint32_t smem_u32(const void* p) {
    uint32_t a;
    asm("{ .reg .u64 t; cvta.to.shared.u64 t, %1; cvt.u32.u64 %0, t; }"
        : "=r"(a) : "l"(p));
    return a;
}
__device__ __forceinline__ void ldsm4(uint32_t a, uint32_t* r) {
    asm volatile("ldmatrix.sync.aligned.m8n8.x4.shared.b16 {%0,%1,%2,%3}, [%4];"
        : "=r"(r[0]), "=r"(r[1]), "=r"(r[2]), "=r"(r[3]) : "r"(a));
}
__device__ __forceinline__ void mma16816(float* c, const uint32_t* a, const uint32_t* b) {
    asm volatile("mma.sync.aligned.m16n8k16.row.col.f32.bf16.bf16.f32 "
        "{%0,%1,%2,%3}, {%4,%5,%6,%7}, {%8,%9}, {%0,%1,%2,%3};"
        : "+f"(c[0]), "+f"(c[1]), "+f"(c[2]), "+f"(c[3])
        : "r"(a[0]), "r"(a[1]), "r"(a[2]), "r"(a[3]), "r"(b[0]), "r"(b[1]));
}
__device__ __forceinline__ uint32_t pack_bf2(float x, float y) {
    __nv_bfloat162 v = __floats2bfloat162_rn(x, y);
    return *reinterpret_cast<uint32_t*>(&v);
}

// ---------------- prep: split weights into bf16 hi/lo --------------------
__global__ void k_cvt(const float* __restrict__ ew1, const float* __restrict__ ew2) {
    int i = blockIdx.x * 256 + threadIdx.x;
    if (i < E*HID*C) {
        float v = ew1[i];
        __nv_bfloat16 h = __float2bfloat16(v);
        g_w1h[i] = h;
        g_w1l[i] = __float2bfloat16(v - __bfloat162float(h));
        v = ew2[i];
        h = __float2bfloat16(v);
        g_w2h[i] = h;
        g_w2l[i] = __float2bfloat16(v - __bfloat162float(h));
    }
}

// ---------------- kernel 0: global-context means + zero counters --------
__global__ void k_gc(const float* __restrict__ x) {
    int bc = blockIdx.x;
    const float4* src = reinterpret_cast<const float4*>(x + (size_t)bc * HW);
    float s = 0.f;
    for (int i = threadIdx.x; i < HW/4; i += 128) {
        float4 v = src[i];
        s += v.x + v.y + v.z + v.w;
    }
    __shared__ float red[4];
    for (int o = 16; o; o >>= 1) s += __shfl_down_sync(0xffffffffu, s, o);
    if ((threadIdx.x & 31) == 0) red[threadIdx.x >> 5] = s;
    __syncthreads();
    if (threadIdx.x == 0) {
        float t = red[0] + red[1] + red[2] + red[3];
        g_gc[bc] = t * (1.0f / HW);
    }
    if (bc == 0 && threadIdx.x < E) {
        g_probsum[threadIdx.x] = 0.f;
        g_loadsum[threadIdx.x] = 0.f;
        g_cnt[threadIdx.x] = 0;
    }
}

// ---------------- kernel A: attention path + router weight folding ------
__global__ void k_attn(const float* __restrict__ proto,
                       const float* __restrict__ ctx_w, const float* __restrict__ ctx_b,
                       const float* __restrict__ inp_w, const float* __restrict__ inp_b,
                       const float* __restrict__ wq, const float* __restrict__ bq,
                       const float* __restrict__ wk, const float* __restrict__ bk,
                       const float* __restrict__ wv, const float* __restrict__ bv,
                       const float* __restrict__ wo, const float* __restrict__ bo,
                       const float* __restrict__ ln_g, const float* __restrict__ ln_b) {
    int b = blockIdx.x;
    int t = threadIdx.x;                       // 256 threads
    __shared__ float seq[SEQ][P], qs[SEQ][P], ks[SEQ][P], vs[SEQ][P], ao[SEQ][P], o2[SEQ][P];
    __shared__ float gx[C];
    __shared__ float mstat[SEQ], istat[SEQ];

    if (t < C) gx[t] = g_gc[b*C + t];
    __syncthreads();

    if (t < P) {
        float a = ctx_b[t];
        for (int c = 0; c < C; c++) a += gx[c] * ctx_w[t*C + c];
        seq[0][t] = a;
    }
    for (int z = t; z < E*P; z += 256) seq[1 + z/P][z%P] = proto[z];
    __syncthreads();

    for (int z = t; z < SEQ*P; z += 256) {
        int s = z >> 6, p = z & 63;
        float aq = bq[p], ak = bk[p], av = bv[p];
        for (int q = 0; q < P; q++) {
            float sv = seq[s][q];
            aq += sv * wq[p*P + q];
            ak += sv * wk[p*P + q];
            av += sv * wv[p*P + q];
        }
        qs[s][p] = aq; ks[s][p] = ak; vs[s][p] = av;
    }
    __syncthreads();

    if (t < NH*SEQ) {
        int n = t / SEQ, i = t % SEQ;
        float sc[SEQ];
        float mx = -1e30f;
        for (int j = 0; j < SEQ; j++) {
            float a = 0.f;
            for (int d = 0; d < HD; d++) a += qs[i][n*HD + d] * ks[j][n*HD + d];
            a *= 0.25f;
            sc[j] = a; mx = fmaxf(mx, a);
        }
        float sm = 0.f;
        for (int j = 0; j < SEQ; j++) { sc[j] = expf(sc[j] - mx); sm += sc[j]; }
        float inv = 1.0f / sm;
        for (int d = 0; d < HD; d++) {
            float a = 0.f;
            for (int j = 0; j < SEQ; j++) a += sc[j] * vs[j][n*HD + d];
            ao[i][n*HD + d] = a * inv;
        }
    }
    __syncthreads();

    for (int z = t; z < SEQ*P; z += 256) {
        int s = z >> 6, p = z & 63;
        float a = bo[p];
        for (int q = 0; q < P; q++) a += ao[s][q] * wo[p*P + q];
        o2[s][p] = a + seq[s][p];
    }
    __syncthreads();

    if (t < SEQ) {
        float m = 0.f;
        for (int p = 0; p < P; p++) m += o2[t][p];
        m *= (1.0f / P);
        float v = 0.f;
        for (int p = 0; p < P; p++) { float d = o2[t][p] - m; v += d*d; }
        v *= (1.0f / P);
        mstat[t] = m; istat[t] = 1.0f / sqrtf(v + 1e-5f);
    }
    __syncthreads();

    for (int z = t; z < E*P; z += 256) {
        int s = z / P + 1, p = z % P;
        seq[s][p] = (o2[s][p] - mstat[s]) * istat[s] * ln_g[p] + ln_b[p];
    }
    __syncthreads();

    for (int z = t; z < E*C; z += 256) {
        int e = z / C, c = z % C;
        float a = 0.f;
        for (int p = 0; p < P; p++) a += seq[e+1][p] * inp_w[p*C + c];
        g_Wr[(b*E + e)*C + c] = a;
    }
    if (t < E) {
        float a = 0.f;
        for (int p = 0; p < P; p++) a += seq[t+1][p] * inp_b[p];
        g_br[b*E + t] = a;
    }
}

// ---------------- kernel B: routing + per-expert compaction -------------
__global__ void k_route(const float* __restrict__ x) {
    int pix = blockIdx.x * 256 + threadIdx.x;
    int b = pix / HW;
    __shared__ float wr[E*C];
    __shared__ float br[E];
    __shared__ float psum[E];
    __shared__ int   scnt[E], sbase[E];
    for (int i = threadIdx.x; i < E*C; i += 256) wr[i] = g_Wr[b*E*C + i];
    if (threadIdx.x < E) {
        br[threadIdx.x] = g_br[b*E + threadIdx.x];
        psum[threadIdx.x] = 0.f;
        scnt[threadIdx.x] = 0;
    }
    __syncthreads();

    float pr[E];
    #pragma unroll
    for (int e = 0; e < E; e++) pr[e] = br[e];
    const float* xp = x + (size_t)b*C*HW + (pix - b*HW);
    for (int c = 0; c < C; c++) {
        float xv = xp[(size_t)c * HW];
        #pragma unroll
        for (int e = 0; e < E; e++) pr[e] += xv * wr[e*C + c];
    }
    float mx = -1e30f;
    #pragma unroll
    for (int e = 0; e < E; e++) { pr[e] *= 0.125f; mx = fmaxf(mx, pr[e]); }
    float sm = 0.f;
    #pragma unroll
    for (int e = 0; e < E; e++) { pr[e] = expf(pr[e] - mx); sm += pr[e]; }
    float invs = 1.0f / sm;
    #pragma unroll
    for (int e = 0; e < E; e++) pr[e] *= invs;

    int used = 0;
    float tsum = 0.f;
    #pragma unroll
    for (int k2 = 0; k2 < KSEL; k2++) {
        float bv = -1.f; int bi = 0;
        #pragma unroll
        for (int e = 0; e < E; e++)
            if (!((used >> e) & 1) && pr[e] > bv) { bv = pr[e]; bi = e; }
        used |= 1 << bi;
        tsum += bv;
    }
    float invt = 1.0f / tsum;

    int loc[E];
    #pragma unroll
    for (int e = 0; e < E; e++) {
        int selq = (used >> e) & 1;
        g_route[(size_t)e * NPIX + pix] = selq ? pr[e] * invt : 0.f;
        atomicAdd(&psum[e], pr[e]);
        loc[e] = selq ? atomicAdd(&scnt[e], 1) : -1;
    }
    __syncthreads();
    if (threadIdx.x < E) {
        int e = threadIdx.x;
        sbase[e] = atomicAdd(&g_cnt[e], scnt[e]);
        atomicAdd(&g_probsum[e], psum[e]);
        atomicAdd(&g_loadsum[e], (float)scnt[e]);
    }
    __syncthreads();
    #pragma unroll
    for (int e = 0; e < E; e++) {
        if (loc[e] >= 0) {
            int slot = sbase[e] + loc[e];
            g_pidx[e*NPIX + slot] = pix;
            g_slot[e*NPIX + pix]  = slot;
        }
    }
}

// ---------------- kernel C: HMMA grouped-GEMM expert MLPs ----------------
// block = (128-slot tile, expert), 8 warps, warp tile 32x64.
// GEMM1 (3 terms hi/lo), gelu, GEMM2 (2 terms: H bf16 single).
// B operands stored [n][k] -> NON-trans ldmatrix (fragment wants consecutive-k).
__global__ void __launch_bounds__(256, 1)
k_mlp(const float* __restrict__ x,
      const float* __restrict__ eb1,
      const float* __restrict__ eb2) {
    extern __shared__ __align__(16) __nv_bfloat16 sm[];
    __nv_bfloat16* Xh = sm;                  // [128][LDT]
    __nv_bfloat16* Xl = Xh + 128*LDT;
    __nv_bfloat16* Wh = Xl + 128*LDT;
    __nv_bfloat16* Wl = Wh + 128*LDT;
    __nv_bfloat16* Hh = Wl + 128*LDT;
    __shared__ int   pid[128];
    __shared__ float bias1[128], bias2[128];

    const int e     = blockIdx.y;
    const int cnt   = g_cnt[e];
    const int tile0 = blockIdx.x * 128;
    if (tile0 >= cnt) return;
    const int rem = min(128, cnt - tile0);
    const int tid = threadIdx.x;
    const int wid = tid >> 5, lane = tid & 31;

    if (tid < 128) {
        pid[tid]   = g_pidx[e*NPIX + tile0 + min(tid, rem - 1)];
        bias2[tid] = eb2[(size_t)e*C + tid];
    }
    __syncthreads();

    // gather X -> bf16 hi/lo [slot][c]
    for (int idx = tid; idx < 128*128; idx += 256) {
        int slot = idx & 127, c = idx >> 7;
        int p = pid[slot];
        int b = p >> 12;
        float v = x[(size_t)b*(C-1)*HW + (size_t)c*HW + p];
        __nv_bfloat16 h = __float2bfloat16(v);
        Xh[slot*LDT + c] = h;
        Xl[slot*LDT + c] = __float2bfloat16(v - __bfloat162float(h));
    }

    const __nv_bfloat16* w1h = g_w1h + (size_t)e*HID*C;
    const __nv_bfloat16* w1l = g_w1l + (size_t)e*HID*C;
    const __nv_bfloat16* w2h = g_w2h + (size_t)e*C*HID;
    const __nv_bfloat16* w2l = g_w2l + (size_t)e*C*HID;

    // warp tile coords
    const int m0 = (wid >> 1) * 32;
    const int n0 = (wid & 1) * 64;
    const int lr = lane & 7, lq = lane >> 3;
    // ldmatrix lane offsets (bytes), stride LDT. Both A and B non-trans.
    // A x4: m0-7/k0 | m8-15/k0 | m0-7/k8 | m8-15/k8
    const int aoff = ((lr + (lq & 1)*8) * LDT + (lq >> 1)*8) * 2;
    // B x4: n0-7/k0 | n0-7/k8 | n8-15/k0 | n8-15/k8
    const int boff = ((lr + (lq >> 1)*8) * LDT + (lq & 1)*8) * 2;
    // epilogue lane coords
    const int er = lane >> 2;
    const int ec = (lane & 3) * 2;

    const uint32_t uXh = smem_u32(Xh), uXl = smem_u32(Xl);
    const uint32_t uWh = smem_u32(Wh), uWl = smem_u32(Wl);
    const uint32_t uHh = smem_u32(Hh);

    const uint32_t aXh = uXh + m0*LDT*2 + aoff;
    const uint32_t aXl = uXl + m0*LDT*2 + aoff;
    const uint32_t aHh = uHh + m0*LDT*2 + aoff;
    const uint32_t bWh = uWh + n0*LDT*2 + boff;
    const uint32_t bWl = uWl + n0*LDT*2 + boff;

    float yacc[2][8][4];
    #pragma unroll
    for (int mt = 0; mt < 2; mt++)
        #pragma unroll
        for (int nt = 0; nt < 8; nt++)
            #pragma unroll
            for (int q = 0; q < 4; q++) yacc[mt][nt][q] = 0.f;

    for (int rc = 0; rc < 4; rc++) {
        const int r0 = rc * 128;
        __syncthreads();   // prev GEMM2 done with Ws; Hh free

        // ---- fill W1 chunk: Ws[n=r local][k=c]
        for (int idx = tid; idx < 128*16; idx += 256) {
            int row = idx >> 4, q = idx & 15;
            *reinterpret_cast<uint4*>(Wh + row*LDT + q*8) =
                *reinterpret_cast<const uint4*>(w1h + (size_t)(r0+row)*C + q*8);
            *reinterpret_cast<uint4*>(Wl + row*LDT + q*8) =
                *reinterpret_cast<const uint4*>(w1l + (size_t)(r0+row)*C + q*8);
        }
        if (tid < 128) bias1[tid] = eb1[(size_t)e*HID + r0 + tid];
        __syncthreads();

        // ---- GEMM1: H[128 slot][128 r] = X @ W1^T  (3 terms)
        float h[2][8][4];
        #pragma unroll
        for (int mt = 0; mt < 2; mt++)
            #pragma unroll
            for (int nt = 0; nt < 8; nt++)
                #pragma unroll
                for (int q = 0; q < 4; q++) h[mt][nt][q] = 0.f;

        #pragma unroll 2
        for (int ks2 = 0; ks2 < 8; ks2++) {
            const uint32_t kb = ks2 * 32;      // 16 bf16 = 32 B
            uint32_t ah[2][4], al[2][4];
            ldsm4(aXh + kb,             ah[0]);
            ldsm4(aXh + kb + 16*LDT*2,  ah[1]);
            ldsm4(aXl + kb,             al[0]);
            ldsm4(aXl + kb + 16*LDT*2,  al[1]);
            #pragma unroll
            for (int ntp = 0; ntp < 4; ntp++) {
                uint32_t bh[4], bl[4];
                ldsm4(bWh + ntp*16*LDT*2 + kb, bh);
                ldsm4(bWl + ntp*16*LDT*2 + kb, bl);
                #pragma unroll
                for (int mt = 0; mt < 2; mt++) {
                    mma16816(h[mt][ntp*2],   ah[mt], bh);
                    mma16816(h[mt][ntp*2+1], ah[mt], bh + 2);
                    mma16816(h[mt][ntp*2],   ah[mt], bl);
                    mma16816(h[mt][ntp*2+1], ah[mt], bl + 2);
                    mma16816(h[mt][ntp*2],   al[mt], bh);
                    mma16816(h[mt][ntp*2+1], al[mt], bh + 2);
                }
            }
        }

        // ---- gelu + bias -> Hh[slot][r] (bf16)
        #pragma unroll
        for (int mt = 0; mt < 2; mt++) {
            #pragma unroll
            for (int nt = 0; nt < 8; nt++) {
                int gm = m0 + mt*16 + er;
                int gn = n0 + nt*8 + ec;
                float b1a = bias1[gn], b1b = bias1[gn+1];
                float u0 = h[mt][nt][0] + b1a;
                float u1 = h[mt][nt][1] + b1b;
                float u2 = h[mt][nt][2] + b1a;
                float u3 = h[mt][nt][3] + b1b;
                u0 = 0.5f*u0*(1.0f + erff(u0*0.70710678118654752f));
                u1 = 0.5f*u1*(1.0f + erff(u1*0.70710678118654752f));
                u2 = 0.5f*u2*(1.0f + erff(u2*0.70710678118654752f));
                u3 = 0.5f*u3*(1.0f + erff(u3*0.70710678118654752f));
                *reinterpret_cast<uint32_t*>(Hh + gm*LDT + gn)     = pack_bf2(u0, u1);
                *reinterpret_cast<uint32_t*>(Hh + (gm+8)*LDT + gn) = pack_bf2(u2, u3);
            }
        }
        __syncthreads();   // Hh visible; GEMM1 Ws reads done

        // ---- fill W2 chunk: Ws[n=c][k=j local]
        for (int idx = tid; idx < 128*16; idx += 256) {
            int row = idx >> 4, q = idx & 15;
            *reinterpret_cast<uint4*>(Wh + row*LDT + q*8) =
                *reinterpret_cast<const uint4*>(w2h + (size_t)row*HID + r0 + q*8);
            *reinterpret_cast<uint4*>(Wl + row*LDT + q*8) =
                *reinterpret_cast<const uint4*>(w2l + (size_t)row*HID + r0 + q*8);
        }
        __syncthreads();

        // ---- GEMM2: Y[128 slot][128 c] += H @ W2chunk^T  (2 terms)
        #pragma unroll 2
        for (int ks2 = 0; ks2 < 8; ks2++) {
            const uint32_t kb = ks2 * 32;
            uint32_t ah[2][4];
            ldsm4(aHh + kb,            ah[0]);
            ldsm4(aHh + kb + 16*LDT*2, ah[1]);
            #pragma unroll
            for (int ntp = 0; ntp < 4; ntp++) {
                uint32_t bh[4], bl[4];
                ldsm4(bWh + ntp*16*LDT*2 + kb, bh);
                ldsm4(bWl + ntp*16*LDT*2 + kb, bl);
                #pragma unroll
                for (int mt = 0; mt < 2; mt++) {
                    mma16816(yacc[mt][ntp*2],   ah[mt], bh);
                    mma16816(yacc[mt][ntp*2+1], ah[mt], bh + 2);
                    mma16816(yacc[mt][ntp*2],   ah[mt], bl);
                    mma16816(yacc[mt][ntp*2+1], ah[mt], bl + 2);
                }
            }
        }
    }

    // ---- epilogue: + eb2, store to g_ybuf[slot][c]
    #pragma unroll
    for (int mt = 0; mt < 2; mt++) {
        #pragma unroll
        for (int nt = 0; nt < 8; nt++) {
            int slot = m0 + mt*16 + er;
            int cc   = n0 + nt*8 + ec;
            float b2a = bias2[cc], b2b = bias2[cc+1];
            if (slot < rem) {
                float2 o = { yacc[mt][nt][0] + b2a, yacc[mt][nt][1] + b2b };
                *reinterpret_cast<float2*>(
                    g_ybuf + ((size_t)e*NPIX + tile0 + slot)*C + cc) = o;
            }
            if (slot + 8 < rem) {
                float2 o = { yacc[mt][nt][2] + b2a, yacc[mt][nt][3] + b2b };
                *reinterpret_cast<float2*>(
                    g_ybuf + ((size_t)e*NPIX + tile0 + slot + 8)*C + cc) = o;
            }
        }
    }
}

// ---------------- kernel G: weighted gather + residual ------------------
__global__ void k_gather(const float* __restrict__ x, float* __restrict__ out) {
    __shared__ float tile[C*33];
    const int t = threadIdx.x;
    const int lane = t & 31, w = t >> 5;
    const int pix0 = blockIdx.x * 32;
    const int b = pix0 >> 12;

    #pragma unroll
    for (int k = 0; k < 4; k++) {
        int px  = w*4 + k;
        int pix = pix0 + px;
        float a0 = 0.f, a1 = 0.f, a2 = 0.f, a3 = 0.f;
        #pragma unroll
        for (int e = 0; e < E; e++) {
            float wv = g_route[(size_t)e*NPIX + pix];
            if (wv > 0.f) {
                int sl = g_slot[e*NPIX + pix];
                const float* row = g_ybuf + ((size_t)e*NPIX + sl)*C;
                a0 += wv * row[lane];
                a1 += wv * row[lane + 32];
                a2 += wv * row[lane + 64];
                a3 += wv * row[lane + 96];
            }
        }
        tile[(lane)*33 + px]      = a0;
        tile[(lane+32)*33 + px]   = a1;
        tile[(lane+64)*33 + px]   = a2;
        tile[(lane+96)*33 + px]   = a3;
    }
    __syncthreads();
    const size_t base = (size_t)b*(C-1)*HW + pix0;
    for (int idx = t; idx < C*32; idx += 256) {
        int c = idx >> 5, px = idx & 31;
        size_t a = base + (size_t)c*HW + px;
        out[a] = x[a] + tile[c*33 + px];
    }
}

// ---------------- kernel D: aux scalar -----------------------------------
__global__ void k_aux(const float* __restrict__ proto, float* __restrict__ out, int out_size) {
    __shared__ float pn[E][P];
    __shared__ float red[128];
    int t = threadIdx.x;
    if (t < E) {
        float s = 0.f;
        for (int p = 0; p < P; p++) { float v = proto[t*P + p]; s += v*v; }
        float inv = 1.0f / sqrtf(s);
        for (int p = 0; p < P; p++) pn[t][p] = proto[t*P + p] * inv;
    }
    __syncthreads();
    float s = 0.f;
    for (int idx = t; idx < E*E; idx += 128) {
        int i = idx / E, j = idx % E;
        float d = 0.f;
        for (int p = 0; p < P; p++) d += pn[i][p] * pn[j][p];
        d -= (i == j) ? 1.0f : 0.0f;
        s += d*d;
    }
    red[t] = s;
    __syncthreads();
    for (int st = 64; st; st >>= 1) { if (t < st) red[t] += red[t + st]; __syncthreads(); }
    if (t == 0) {
        float ortho = sqrtf(red[0]);
        float aux = 0.f;
        for (int e = 0; e < E; e++)
            aux += (g_probsum[e] * (1.0f/NPIX)) * (g_loadsum[e] * (1.0f/NPIX));
        aux *= (float)E;
        if (out_size > BB*C*HW) out[BB*C*HW] = aux + 0.5f * ortho;
    }
}

// ---------------- launcher ------------------------------------------------
extern "C" void kernel_launch(void* const* d_in, const int* in_sizes, int n_in,
                              void* d_out, int out_size) {
    const float* x      = (const float*)d_in[0];
    const float* proto  = (const float*)d_in[1];
    const float* ctx_w  = (const float*)d_in[2];
    const float* ctx_b  = (const float*)d_in[3];
    const float* inp_w  = (const float*)d_in[4];
    const float* inp_b  = (const float*)d_in[5];
    const float* wq     = (const float*)d_in[6];
    const float* bq     = (const float*)d_in[7];
    const float* wk     = (const float*)d_in[8];
    const float* bk     = (const float*)d_in[9];
    const float* wv     = (const float*)d_in[10];
    const float* bv     = (const float*)d_in[11];
    const float* wo     = (const float*)d_in[12];
    const float* bo     = (const float*)d_in[13];
    const float* ln_g   = (const float*)d_in[14];
    const float* ln_b   = (const float*)d_in[15];
    const float* ew1    = (const float*)d_in[16];
    const float* eb1    = (const float*)d_in[17];
    const float* ew2    = (const float*)d_in[18];
    const float* eb2    = (const float*)d_in[19];
    float* out = (float*)d_out;

    const int smem_mlp = 5 * 128 * LDT * (int)sizeof(__nv_bfloat16);  // 174080 B
    cudaFuncSetAttribute(k_mlp, cudaFuncAttributeMaxDynamicSharedMemorySize, smem_mlp);

    k_cvt<<<(E*HID*C + 255)/256, 256>>>(ew1, ew2);
    k_gc<<<BB*C, 128>>>(x);
    k_attn<<<BB, 256>>>(proto, ctx_w, ctx_b, inp_w, inp_b,
                        wq, bq, wk, bk, wv, bv, wo, bo, ln_g, ln_b);
    k_route<<<NPIX/256, 256>>>(x);
    k_mlp<<<dim3(NPIX/128, E), 256, smem_mlp>>>(x, eb1, eb2);
    k_gather<<<NPIX/32, 256>>>(x, out);
    k_aux<<<1, 128>>>(proto, out, out_size);
}